// round 3
// baseline (speedup 1.0000x reference)
#include <cuda_runtime.h>
#include <math.h>

// Problem constants (B=1024, R=10, L=512)
#define BB   1024
#define RR   10
#define LL   512
#define KK   1024      // 2L
#define BRD  10240     // B*R

// GEMM tiling: BM=128 rows, BN=128 cols (64 u + 64 v), BK=16, 128 threads
#define BM 128
#define BK 16
#define NCHUNK 8       // 512/64 l-values per block

// Scratch (static device memory; no allocation allowed)
__device__ float g_tpart[2][BRD][NCHUNK];  // per-row partial weighted sums
__device__ float g_wvec[2][LL];            // [0]=wh=W1[:L]@W2, [1]=wq=W1[L:]@W2
__device__ float g_c0;                     // b1.W2 + b2

// ---------------------------------------------------------------------------
// Prep: wh, wq, c0 — one warp per output, warp-shuffle reduction.
// ---------------------------------------------------------------------------
__global__ __launch_bounds__(128)
void prep_kernel(const float* __restrict__ W1, const float* __restrict__ b1,
                 const float* __restrict__ W2, const float* __restrict__ b2)
{
    const int warp = threadIdx.x >> 5;
    const int lane = threadIdx.x & 31;
    const int idx  = blockIdx.x * 4 + warp;      // 0..1023 = row of W1

    float s = 0.f;
    #pragma unroll 4
    for (int m = lane; m < LL; m += 32)
        s += W1[(size_t)idx * LL + m] * W2[m];
    #pragma unroll
    for (int o = 16; o > 0; o >>= 1)
        s += __shfl_down_sync(0xFFFFFFFF, s, o);
    if (lane == 0) {
        if (idx < LL) g_wvec[0][idx] = s;
        else          g_wvec[1][idx - LL] = s;
    }

    if (blockIdx.x == 0 && warp == 0) {
        float c = 0.f;
        #pragma unroll 4
        for (int m = lane; m < LL; m += 32)
            c += b1[m] * W2[m];
        #pragma unroll
        for (int o = 16; o > 0; o >>= 1)
            c += __shfl_down_sync(0xFFFFFFFF, c, o);
        if (lane == 0) g_c0 = c + b2[0];
    }
}

// ---------------------------------------------------------------------------
// Packed f32x2 helpers
// ---------------------------------------------------------------------------
__device__ __forceinline__ unsigned long long bcast2(float x) {
    unsigned long long r;
    unsigned int xb = __float_as_uint(x);
    asm("mov.b64 %0, {%1, %1};" : "=l"(r) : "r"(xb));
    return r;
}
__device__ __forceinline__ void fma2(unsigned long long& d,
                                     unsigned long long a, unsigned long long b) {
    asm("fma.rn.f32x2 %0, %1, %2, %3;" : "=l"(d) : "l"(a), "l"(b), "l"(d));
}
__device__ __forceinline__ void unpack2(unsigned long long v, float& lo, float& hi) {
    unsigned int l, h;
    asm("mov.b64 {%0, %1}, %2;" : "=r"(l), "=r"(h) : "l"(v));
    lo = __uint_as_float(l);
    hi = __uint_as_float(h);
}

// ---------------------------------------------------------------------------
// Fused gated-transform GEMM + weighted reduction.
// 128-thread CTA computes 128 rows x 64 l's (u and v for each l).
// Thread tile: 8 rows x (8 u-cols + 8 v-cols) = 8x16, packed f32x2 FMAs.
// grid = (80, 8, 2)
// ---------------------------------------------------------------------------
__global__ __launch_bounds__(128)
void gemm_kernel(const float* __restrict__ hist, const float* __restrict__ ques,
                 const float* __restrict__ Wy_h, const float* __restrict__ by_h,
                 const float* __restrict__ Wg_h, const float* __restrict__ bg_h,
                 const float* __restrict__ Wy_q, const float* __restrict__ by_q,
                 const float* __restrict__ Wg_q, const float* __restrict__ bg_q)
{
    __shared__ float As[BK][132];    // padded: stride 132 kills STS bank conflicts
    __shared__ float Bs[BK][128];    // cols [0,64)=Wy chunk, [64,128)=Wg chunk

    const int input = blockIdx.z;
    const int l0    = blockIdx.y * 64;
    const int m0    = blockIdx.x * BM;

    const float* X  = input ? ques : hist;
    const float* Wy = input ? Wy_q : Wy_h;
    const float* Wg = input ? Wg_q : Wg_h;
    const float* by = input ? by_q : by_h;
    const float* bg = input ? bg_q : bg_h;

    const int tid = threadIdx.x;     // 0..127
    const int tx  = tid & 7;         // 0..7  (8 l's per thread)
    const int ty  = tid >> 3;        // 0..15 (8 rows per thread)

    // accp[p][j]: row-pair p (rows ty*8+2p, +1); j<8: u-cols, j>=8: v-cols
    unsigned long long accp[4][16];
    #pragma unroll
    for (int p = 0; p < 4; p++)
        #pragma unroll
        for (int j = 0; j < 16; j++) accp[p][j] = 0ULL;

    for (int k0 = 0; k0 < KK; k0 += BK) {
        // ---- X tile -> As (transposed, padded stride) ----
        #pragma unroll
        for (int qq = 0; qq < 4; qq++) {
            int row = qq * 32 + (tid >> 2);
            int kq  = tid & 3;
            float4 v = *(const float4*)&X[(size_t)(m0 + row) * KK + k0 + kq * 4];
            As[kq * 4 + 0][row] = v.x;
            As[kq * 4 + 1][row] = v.y;
            As[kq * 4 + 2][row] = v.z;
            As[kq * 4 + 3][row] = v.w;
        }
        // ---- W tile -> Bs: cols [0,64) Wy, [64,128) Wg (lane-coalesced) ----
        #pragma unroll
        for (int qq = 0; qq < 4; qq++) {
            int k = qq * 4 + (tid >> 5);
            int j = (tid & 31) * 4;
            const float* src = (j < 64)
                ? &Wy[(size_t)(k0 + k) * LL + l0 + j]
                : &Wg[(size_t)(k0 + k) * LL + l0 + (j - 64)];
            *(float4*)&Bs[k][j] = *(const float4*)src;
        }
        __syncthreads();

        #pragma unroll
        for (int k = 0; k < BK; k++) {
            unsigned long long a2[4];
            const unsigned long long* ap = (const unsigned long long*)&As[k][ty * 8];
            a2[0] = ap[0]; a2[1] = ap[1]; a2[2] = ap[2]; a2[3] = ap[3];

            float4 u0 = *(const float4*)&Bs[k][tx * 8];
            float4 u1 = *(const float4*)&Bs[k][tx * 8 + 4];
            float4 v0 = *(const float4*)&Bs[k][64 + tx * 8];
            float4 v1 = *(const float4*)&Bs[k][64 + tx * 8 + 4];
            float bf[16] = {u0.x, u0.y, u0.z, u0.w, u1.x, u1.y, u1.z, u1.w,
                            v0.x, v0.y, v0.z, v0.w, v1.x, v1.y, v1.z, v1.w};
            #pragma unroll
            for (int j = 0; j < 16; j++) {
                unsigned long long bb = bcast2(bf[j]);
                fma2(accp[0][j], a2[0], bb);
                fma2(accp[1][j], a2[1], bb);
                fma2(accp[2][j], a2[2], bb);
                fma2(accp[3][j], a2[3], bb);
            }
        }
        __syncthreads();
    }

    // ---- epilogue: tanh(u+by)*sigmoid(v+bg)*w over this thread's 8 l's ----
    const int gl = l0 + tx * 8;
    const float* w = g_wvec[input];
    float wv[8], byv[8], bgv[8];
    #pragma unroll
    for (int c = 0; c < 8; c++) {
        wv[c]  = w[gl + c];
        byv[c] = by[gl + c];
        bgv[c] = bg[gl + c];
    }
    float part[8];
    #pragma unroll
    for (int p = 0; p < 4; p++) {
        float su[2] = {0.f, 0.f};
        #pragma unroll
        for (int c = 0; c < 8; c++) {
            float ulo, uhi, vlo, vhi;
            unpack2(accp[p][c],     ulo, uhi);
            unpack2(accp[p][8 + c], vlo, vhi);
            float uu0 = ulo + byv[c], vv0 = vlo + bgv[c];
            float uu1 = uhi + byv[c], vv1 = vhi + bgv[c];
            su[0] += tanhf(uu0) * (1.f / (1.f + expf(-vv0))) * wv[c];
            su[1] += tanhf(uu1) * (1.f / (1.f + expf(-vv1))) * wv[c];
        }
        part[2 * p]     = su[0];
        part[2 * p + 1] = su[1];
    }

    // ---- deterministic cross-thread reduction (8 column-groups per row) ----
    float* red = &As[0][0];   // reuse smem (>=1024 floats)
    #pragma unroll
    for (int i = 0; i < 8; i++) red[tx * BM + ty * 8 + i] = part[i];
    __syncthreads();
    if (tx == 0) {
        #pragma unroll
        for (int i = 0; i < 8; i++) {
            float s = 0.f;
            #pragma unroll
            for (int x = 0; x < 8; x++) s += red[x * BM + ty * 8 + i];
            g_tpart[input][m0 + ty * 8 + i][blockIdx.y] = s;
        }
    }
}

// ---------------------------------------------------------------------------
// Final: logits + Gumbel, argmax over prefix, one-hot write.
// ---------------------------------------------------------------------------
__global__ void final_kernel(const float* __restrict__ noise,
                             const float* __restrict__ Wa, const float* __restrict__ ba,
                             float* __restrict__ out)
{
    int t = blockIdx.x * blockDim.x + threadIdx.x;
    if (t >= BRD) return;
    int b = t / RR;
    int i = t % RR;

    float Wa0 = Wa[0], Wa1 = Wa[1], ba0 = ba[0], c0 = g_c0;

    float tq = 0.f;
    #pragma unroll
    for (int c = 0; c < NCHUNK; c++) tq += g_tpart[1][t][c];

    float best = -3.4e38f;
    int bj = 0;
    for (int j = 0; j <= i; j++) {
        float th = 0.f;
        #pragma unroll
        for (int c = 0; c < NCHUNK; c++) th += g_tpart[0][b * RR + j][c];
        float score = tq + th + c0;
        float logit = score * Wa0 + (float)(i - j + 1) * Wa1 + ba0;
        float ns = noise[(size_t)b * RR * RR + i * RR + j];
        float g  = -logf(1e-10f - logf(ns + 1e-10f));
        float z  = logit + g;
        if (z > best) { best = z; bj = j; }   // strict > keeps first max
    }

    float* o = out + (size_t)b * RR * RR + (size_t)i * RR;
    #pragma unroll
    for (int j = 0; j < RR; j++) o[j] = (j == bj) ? 1.f : 0.f;
}

// ---------------------------------------------------------------------------
extern "C" void kernel_launch(void* const* d_in, const int* in_sizes, int n_in,
                              void* d_out, int out_size)
{
    const float* hist  = (const float*)d_in[0];
    const float* ques  = (const float*)d_in[1];
    const float* noise = (const float*)d_in[2];
    const float* Wy_h  = (const float*)d_in[3];
    const float* by_h  = (const float*)d_in[4];
    const float* Wg_h  = (const float*)d_in[5];
    const float* bg_h  = (const float*)d_in[6];
    const float* Wy_q  = (const float*)d_in[7];
    const float* by_q  = (const float*)d_in[8];
    const float* Wg_q  = (const float*)d_in[9];
    const float* bg_q  = (const float*)d_in[10];
    const float* W1    = (const float*)d_in[11];
    const float* b1    = (const float*)d_in[12];
    const float* W2    = (const float*)d_in[13];
    const float* b2    = (const float*)d_in[14];
    const float* Wa    = (const float*)d_in[15];
    const float* ba    = (const float*)d_in[16];
    float* out = (float*)d_out;

    prep_kernel<<<256, 128>>>(W1, b1, W2, b2);

    dim3 grid(BRD / BM, NCHUNK, 2);
    gemm_kernel<<<grid, 128>>>(hist, ques,
                               Wy_h, by_h, Wg_h, bg_h,
                               Wy_q, by_q, Wg_q, bg_q);

    final_kernel<<<(BRD + 255) / 256, 256>>>(noise, Wa, ba, out);
}

// round 5
// speedup vs baseline: 2.4314x; 2.4314x over previous
#include <cuda_runtime.h>
#include <cuda_fp16.h>
#include <math.h>
#include <stdint.h>

// Problem constants (B=1024, R=10, L=512)
#define RR   10
#define LL   512
#define KK   1024      // 2L
#define BRD  10240     // B*R
#define NLCH 8         // l-chunks of 64
#define NKCH 48        // 3 plane-pairs * 16 k-chunks of 64 halves

// ---------------------------------------------------------------------------
// Static device scratch (no runtime allocation allowed)
// ---------------------------------------------------------------------------
__device__ __half g_Xh[2][BRD][KK];     // fp16 hi plane of X
__device__ __half g_Xl[2][BRD][KK];     // fp16 lo plane of X
__device__ __half g_Wh[2][1024][KK];    // fp16 hi plane of 1024*W^T  (n<512: Wy, n>=512: Wg)
__device__ __half g_Wl[2][1024][KK];    // fp16 lo plane
__device__ float  g_tpart[2][BRD][NLCH];
__device__ float  g_wvec[2][LL];        // [0]=wh=W1[:L]@W2, [1]=wq=W1[L:]@W2
__device__ float  g_c0;                 // b1.W2 + b2

// ---------------------------------------------------------------------------
// helpers
// ---------------------------------------------------------------------------
__device__ __forceinline__ uint32_t smem_u32(const void* p) {
    uint32_t a;
    asm("{ .reg .u64 t; cvta.to.shared.u64 t, %1; cvt.u32.u64 %0, t; }" : "=r"(a) : "l"(p));
    return a;
}
#define SWZ(o) ((uint32_t)(o) ^ ((((uint32_t)(o)) >> 3) & 0x70))

__device__ __forceinline__ void cp16(uint32_t dst, const void* src) {
    asm volatile("cp.async.cg.shared.global [%0], [%1], 16;" :: "r"(dst), "l"(src) : "memory");
}
#define CP_COMMIT() asm volatile("cp.async.commit_group;" ::: "memory")

#define LDSM4(r0, r1, r2, r3, addr) \
    asm volatile("ldmatrix.sync.aligned.m8n8.x4.shared.b16 {%0,%1,%2,%3}, [%4];" \
                 : "=r"(r0), "=r"(r1), "=r"(r2), "=r"(r3) : "r"(addr))

#define MMA16816(c, a0, a1, a2, a3, b0, b1) \
    asm volatile("mma.sync.aligned.m16n8k16.row.col.f32.f16.f16.f32 " \
                 "{%0,%1,%2,%3}, {%4,%5,%6,%7}, {%8,%9}, {%0,%1,%2,%3};" \
                 : "+f"((c)[0]), "+f"((c)[1]), "+f"((c)[2]), "+f"((c)[3]) \
                 : "r"(a0), "r"(a1), "r"(a2), "r"(a3), "r"(b0), "r"(b1))

// ---------------------------------------------------------------------------
// Prep: wvec, c0
// ---------------------------------------------------------------------------
__global__ __launch_bounds__(128)
void prep_kernel(const float* __restrict__ W1, const float* __restrict__ b1,
                 const float* __restrict__ W2, const float* __restrict__ b2)
{
    const int warp = threadIdx.x >> 5;
    const int lane = threadIdx.x & 31;
    const int idx  = blockIdx.x * 4 + warp;
    float s = 0.f;
    #pragma unroll 4
    for (int m = lane; m < LL; m += 32)
        s += W1[(size_t)idx * LL + m] * W2[m];
    #pragma unroll
    for (int o = 16; o > 0; o >>= 1) s += __shfl_down_sync(0xFFFFFFFF, s, o);
    if (lane == 0) {
        if (idx < LL) g_wvec[0][idx] = s;
        else          g_wvec[1][idx - LL] = s;
    }
    if (blockIdx.x == 0 && warp == 0) {
        float c = 0.f;
        #pragma unroll 4
        for (int m = lane; m < LL; m += 32) c += b1[m] * W2[m];
        #pragma unroll
        for (int o = 16; o > 0; o >>= 1) c += __shfl_down_sync(0xFFFFFFFF, c, o);
        if (lane == 0) g_c0 = c + b2[0];
    }
}

// ---------------------------------------------------------------------------
// X conversion: fp32 -> fp16 hi/lo planes. grid (10240, 2), block 256.
// ---------------------------------------------------------------------------
__global__ __launch_bounds__(256)
void xconv_kernel(const float* __restrict__ hist, const float* __restrict__ ques)
{
    const int input = blockIdx.y;
    const int row   = blockIdx.x;
    const int t     = threadIdx.x;
    const float* X  = input ? ques : hist;
    float4 f = *(const float4*)(X + (size_t)row * KK + t * 4);
    float fv[4] = {f.x, f.y, f.z, f.w};
    __half h[4], l[4];
    #pragma unroll
    for (int e = 0; e < 4; e++) {
        h[e] = __float2half_rn(fv[e]);
        l[e] = __float2half_rn(fv[e] - __half2float(h[e]));
    }
    *(uint2*)&g_Xh[input][row][t * 4] = *(uint2*)h;
    *(uint2*)&g_Xl[input][row][t * 4] = *(uint2*)l;
}

// ---------------------------------------------------------------------------
// W conversion: fp32 [k][l] -> fp16 hi/lo planes of (1024*W)^T, [n][k].
// grid (32 ktiles, 32 ntiles, 2), block (32, 8)
// ---------------------------------------------------------------------------
__global__ __launch_bounds__(256)
void wconv_kernel(const float* __restrict__ Wy_h, const float* __restrict__ Wg_h,
                  const float* __restrict__ Wy_q, const float* __restrict__ Wg_q)
{
    __shared__ float tile[32][33];
    const int tx = threadIdx.x, ty = threadIdx.y;
    const int kt = blockIdx.x, nt = blockIdx.y, inp = blockIdx.z;
    const float* W;
    int lbase;
    if (nt * 32 < 512) { W = inp ? Wy_q : Wy_h; lbase = nt * 32; }
    else               { W = inp ? Wg_q : Wg_h; lbase = nt * 32 - 512; }
    #pragma unroll
    for (int r = 0; r < 4; r++)
        tile[ty + r * 8][tx] = W[(size_t)(kt * 32 + ty + r * 8) * 512 + lbase + tx];
    __syncthreads();
    #pragma unroll
    for (int r = 0; r < 4; r++) {
        int nl = ty + r * 8;
        int n  = nt * 32 + nl;
        int k  = kt * 32 + tx;
        float f = tile[tx][nl] * 1024.0f;          // scale avoids fp16 denormal lo
        __half hi = __float2half_rn(f);
        __half lo = __float2half_rn(f - __half2float(hi));
        g_Wh[inp][n][k] = hi;
        g_Wl[inp][n][k] = lo;
    }
}

// ---------------------------------------------------------------------------
// HMMA GEMM + fused gated epilogue.
// CTA: 128 rows x 128 cols (64 u-l's + 64 v-l's), K-loop = 48 chunks of 64
// halves across 3 plane pairs: (Xh,Wh), (Xl,Wh), (Xh,Wl).
// grid (80, 8, 2), block 256 (8 warps, each m16 x n128).
// smem: 2 stages x (A 16KB + B 16KB) = 64KB, SW128 swizzled.
// ---------------------------------------------------------------------------
__global__ __launch_bounds__(256)
void gemm_hmma(const float* __restrict__ by_h, const float* __restrict__ bg_h,
               const float* __restrict__ by_q, const float* __restrict__ bg_q)
{
    extern __shared__ char smem[];
    const uint32_t sbase = smem_u32(smem);
    const int tid = threadIdx.x, wid = tid >> 5, lane = tid & 31;
    const int input = blockIdx.z, lc = blockIdx.y;
    const int m0 = blockIdx.x * 128;

    const __half* Xh = &g_Xh[input][0][0];
    const __half* Xl = &g_Xl[input][0][0];
    const __half* Wh = &g_Wh[input][0][0];
    const __half* Wl = &g_Wl[input][0][0];
    const float* by_ = input ? by_q : by_h;
    const float* bg_ = input ? bg_q : bg_h;

    // per-thread load indices (8 x 16B per chunk: 4 for A, 4 for B)
    const int ldrow = tid >> 3;        // 0..31 (+i*32)
    const int ldseg = tid & 7;

    // fragment lane decomposition
    const int q  = lane >> 3;          // ldmatrix lane group
    const int r  = lane & 7;
    const int tq = lane & 3;           // quad thread
    const int g  = lane >> 2;          // quad group (row within tile)
    const int rw = wid * 16;

    const uint32_t rx     = (uint32_t)(r << 4);            // swizzle xor (row&7)<<4
    const uint32_t a_rowo = (uint32_t)((rw + (q & 1) * 8 + r) * 128);
    const uint32_t aq16   = (uint32_t)((q >> 1) * 16);
    const uint32_t b_rowo = (uint32_t)(((q >> 1) * 8 + r) * 128);
    const uint32_t bq16   = (uint32_t)((q & 1) * 16);

    float c[16][4];
    #pragma unroll
    for (int j = 0; j < 16; j++)
        #pragma unroll
        for (int e = 0; e < 4; e++) c[j][e] = 0.f;

    // ---- chunk loader ----
    auto load_chunk = [&](int kc) {
        const int st = kc & 1;
        const int p  = kc >> 4;
        const int ko = (kc & 15) * 64;
        const __half* As = (p == 1) ? Xl : Xh;
        const __half* Bs = (p == 2) ? Wl : Wh;
        const uint32_t sa = sbase + st * 32768;
        const uint32_t sb = sa + 16384;
        #pragma unroll
        for (int i = 0; i < 4; i++) {
            int row = i * 32 + ldrow;
            const void* src = As + ((size_t)(m0 + row) << 10) + ko + ldseg * 8;
            cp16(sa + SWZ(row * 128 + ldseg * 16), src);
        }
        #pragma unroll
        for (int i = 0; i < 4; i++) {
            int row = i * 32 + ldrow;
            int ng  = (row < 64) ? (lc * 64 + row) : (448 + lc * 64 + row);
            const void* src = Bs + ((size_t)ng << 10) + ko + ldseg * 8;
            cp16(sb + SWZ(row * 128 + ldseg * 16), src);
        }
        CP_COMMIT();
    };

    load_chunk(0);

    #pragma unroll 1
    for (int kc = 0; kc < NKCH; kc++) {
        __syncthreads();                       // stage (kc+1)&1 free for reuse
        if (kc + 1 < NKCH) {
            load_chunk(kc + 1);
            asm volatile("cp.async.wait_group 1;" ::: "memory");
        } else {
            asm volatile("cp.async.wait_group 0;" ::: "memory");
        }
        __syncthreads();                       // chunk kc visible to all

        const uint32_t sa = sbase + (kc & 1) * 32768;
        const uint32_t sb = sa + 16384;

        #pragma unroll
        for (int s = 0; s < 4; s++) {
            const uint32_t cba = ((uint32_t)(s * 32) + aq16) ^ rx;
            const uint32_t cbb = ((uint32_t)(s * 32) + bq16) ^ rx;
            uint32_t a0, a1, a2, a3;
            LDSM4(a0, a1, a2, a3, sa + a_rowo + cba);
            #pragma unroll
            for (int nt = 0; nt < 8; nt++) {
                uint32_t b0, b1, b2, b3;
                LDSM4(b0, b1, b2, b3, sb + (uint32_t)(nt * 2048) + b_rowo + cbb);
                MMA16816(c[2 * nt],     a0, a1, a2, a3, b0, b1);
                MMA16816(c[2 * nt + 1], a0, a1, a2, a3, b2, b3);
            }
        }
    }

    // ---- fused epilogue: u = acc/1024 + by; v likewise; sum tanh(u)*sig(v)*w ----
    const float INV = 1.0f / 1024.0f;
    float p0 = 0.f, p1 = 0.f;
    #pragma unroll
    for (int j = 0; j < 8; j++) {
        #pragma unroll
        for (int e = 0; e < 2; e++) {
            int l = lc * 64 + j * 8 + tq * 2 + e;
            float byv = __ldg(by_ + l);
            float bgv = __ldg(bg_ + l);
            float wv  = g_wvec[input][l];
            float u0 = c[j][e] * INV + byv;
            float v0 = c[j + 8][e] * INV + bgv;
            p0 += tanhf(u0) * (1.f / (1.f + expf(-v0))) * wv;
            float u1 = c[j][2 + e] * INV + byv;
            float v1 = c[j + 8][2 + e] * INV + bgv;
            p1 += tanhf(u1) * (1.f / (1.f + expf(-v1))) * wv;
        }
    }
    // reduce across the 4 quad-threads (deterministic order)
    p0 += __shfl_down_sync(0xFFFFFFFF, p0, 2);
    p0 += __shfl_down_sync(0xFFFFFFFF, p0, 1);
    p1 += __shfl_down_sync(0xFFFFFFFF, p1, 2);
    p1 += __shfl_down_sync(0xFFFFFFFF, p1, 1);
    if (tq == 0) {
        g_tpart[input][m0 + rw + g][lc]     = p0;
        g_tpart[input][m0 + rw + g + 8][lc] = p1;
    }
}

// ---------------------------------------------------------------------------
// Final: logits + Gumbel, argmax over prefix, one-hot write.
// ---------------------------------------------------------------------------
__global__ void final_kernel(const float* __restrict__ noise,
                             const float* __restrict__ Wa, const float* __restrict__ ba,
                             float* __restrict__ out)
{
    int t = blockIdx.x * blockDim.x + threadIdx.x;
    if (t >= BRD) return;
    int b = t / RR;
    int i = t % RR;

    float Wa0 = Wa[0], Wa1 = Wa[1], ba0 = ba[0], c0 = g_c0;
    float tq = 0.f;
    #pragma unroll
    for (int c = 0; c < NLCH; c++) tq += g_tpart[1][t][c];

    float best = -3.4e38f;
    int bj = 0;
    for (int j = 0; j <= i; j++) {
        float th = 0.f;
        #pragma unroll
        for (int c = 0; c < NLCH; c++) th += g_tpart[0][b * RR + j][c];
        float score = tq + th + c0;
        float logit = score * Wa0 + (float)(i - j + 1) * Wa1 + ba0;
        float ns = noise[(size_t)b * RR * RR + i * RR + j];
        float gm = -logf(1e-10f - logf(ns + 1e-10f));
        float z  = logit + gm;
        if (z > best) { best = z; bj = j; }   // strict > keeps first max
    }
    float* o = out + (size_t)b * RR * RR + (size_t)i * RR;
    #pragma unroll
    for (int j = 0; j < RR; j++) o[j] = (j == bj) ? 1.f : 0.f;
}

// ---------------------------------------------------------------------------
extern "C" void kernel_launch(void* const* d_in, const int* in_sizes, int n_in,
                              void* d_out, int out_size)
{
    const float* hist  = (const float*)d_in[0];
    const float* ques  = (const float*)d_in[1];
    const float* noise = (const float*)d_in[2];
    const float* Wy_h  = (const float*)d_in[3];
    const float* by_h  = (const float*)d_in[4];
    const float* Wg_h  = (const float*)d_in[5];
    const float* bg_h  = (const float*)d_in[6];
    const float* Wy_q  = (const float*)d_in[7];
    const float* by_q  = (const float*)d_in[8];
    const float* Wg_q  = (const float*)d_in[9];
    const float* bg_q  = (const float*)d_in[10];
    const float* W1    = (const float*)d_in[11];
    const float* b1    = (const float*)d_in[12];
    const float* W2    = (const float*)d_in[13];
    const float* b2    = (const float*)d_in[14];
    const float* Wa    = (const float*)d_in[15];
    const float* ba    = (const float*)d_in[16];
    float* out = (float*)d_out;

    cudaFuncSetAttribute(gemm_hmma, cudaFuncAttributeMaxDynamicSharedMemorySize, 65536);

    prep_kernel<<<256, 128>>>(W1, b1, W2, b2);
    xconv_kernel<<<dim3(BRD, 2), 256>>>(hist, ques);
    wconv_kernel<<<dim3(32, 32, 2), dim3(32, 8)>>>(Wy_h, Wg_h, Wy_q, Wg_q);

    gemm_hmma<<<dim3(80, NLCH, 2), 256, 65536>>>(by_h, bg_h, by_q, bg_q);

    final_kernel<<<(BRD + 255) / 256, 256>>>(noise, Wa, ba, out);
}

// round 6
// speedup vs baseline: 2.6673x; 1.0970x over previous
#include <cuda_runtime.h>
#include <cuda_fp16.h>
#include <math.h>
#include <stdint.h>

// Problem constants (B=1024, R=10, L=512)
#define RR   10
#define LL   512
#define KK   1024      // 2L
#define BRD  10240     // B*R
#define NLCH 8         // l-chunks of 64
#define NKCH 48        // 3 plane-pairs * 16 k-chunks of 64 halves

// ---------------------------------------------------------------------------
// Static device scratch (no runtime allocation allowed)
// ---------------------------------------------------------------------------
__device__ __half g_Xh[2][BRD][KK];     // fp16 hi plane of X
__device__ __half g_Xl[2][BRD][KK];     // fp16 lo plane of X
__device__ __half g_Wh[2][1024][KK];    // fp16 hi plane of 1024*W^T (n<512: Wy, else Wg)
__device__ __half g_Wl[2][1024][KK];    // fp16 lo plane
__device__ float  g_tpart[2][BRD][NLCH];
__device__ float  g_wvec[2][LL];        // [0]=wh=W1[:L]@W2, [1]=wq=W1[L:]@W2
__device__ float  g_c0;                 // b1.W2 + b2

// ---------------------------------------------------------------------------
// helpers
// ---------------------------------------------------------------------------
__device__ __forceinline__ uint32_t smem_u32(const void* p) {
    uint32_t a;
    asm("{ .reg .u64 t; cvta.to.shared.u64 t, %1; cvt.u32.u64 %0, t; }" : "=r"(a) : "l"(p));
    return a;
}
#define SWZ(o) ((uint32_t)(o) ^ ((((uint32_t)(o)) >> 3) & 0x70))

__device__ __forceinline__ void cp16(uint32_t dst, const void* src) {
    asm volatile("cp.async.cg.shared.global [%0], [%1], 16;" :: "r"(dst), "l"(src) : "memory");
}
#define CP_COMMIT() asm volatile("cp.async.commit_group;" ::: "memory")

#define LDSM4(r0, r1, r2, r3, addr) \
    asm volatile("ldmatrix.sync.aligned.m8n8.x4.shared.b16 {%0,%1,%2,%3}, [%4];" \
                 : "=r"(r0), "=r"(r1), "=r"(r2), "=r"(r3) : "r"(addr))

#define MMA16816(c, a0, a1, a2, a3, b0, b1) \
    asm volatile("mma.sync.aligned.m16n8k16.row.col.f32.f16.f16.f32 " \
                 "{%0,%1,%2,%3}, {%4,%5,%6,%7}, {%8,%9}, {%0,%1,%2,%3};" \
                 : "+f"((c)[0]), "+f"((c)[1]), "+f"((c)[2]), "+f"((c)[3]) \
                 : "r"(a0), "r"(a1), "r"(a2), "r"(a3), "r"(b0), "r"(b1))

// ---------------------------------------------------------------------------
// Prep: wvec, c0
// ---------------------------------------------------------------------------
__global__ __launch_bounds__(128)
void prep_kernel(const float* __restrict__ W1, const float* __restrict__ b1,
                 const float* __restrict__ W2, const float* __restrict__ b2)
{
    const int warp = threadIdx.x >> 5;
    const int lane = threadIdx.x & 31;
    const int idx  = blockIdx.x * 4 + warp;
    float s = 0.f;
    #pragma unroll 4
    for (int m = lane; m < LL; m += 32)
        s += W1[(size_t)idx * LL + m] * W2[m];
    #pragma unroll
    for (int o = 16; o > 0; o >>= 1) s += __shfl_down_sync(0xFFFFFFFF, s, o);
    if (lane == 0) {
        if (idx < LL) g_wvec[0][idx] = s;
        else          g_wvec[1][idx - LL] = s;
    }
    if (blockIdx.x == 0 && warp == 0) {
        float c = 0.f;
        #pragma unroll 4
        for (int m = lane; m < LL; m += 32) c += b1[m] * W2[m];
        #pragma unroll
        for (int o = 16; o > 0; o >>= 1) c += __shfl_down_sync(0xFFFFFFFF, c, o);
        if (lane == 0) g_c0 = c + b2[0];
    }
}

// ---------------------------------------------------------------------------
// X conversion: fp32 -> fp16 hi/lo planes. grid (10240, 2), block 256.
// ---------------------------------------------------------------------------
__global__ __launch_bounds__(256)
void xconv_kernel(const float* __restrict__ hist, const float* __restrict__ ques)
{
    const int input = blockIdx.y;
    const int row   = blockIdx.x;
    const int t     = threadIdx.x;
    const float* X  = input ? ques : hist;
    float4 f = *(const float4*)(X + (size_t)row * KK + t * 4);
    float fv[4] = {f.x, f.y, f.z, f.w};
    __half h[4], l[4];
    #pragma unroll
    for (int e = 0; e < 4; e++) {
        h[e] = __float2half_rn(fv[e]);
        l[e] = __float2half_rn(fv[e] - __half2float(h[e]));
    }
    *(uint2*)&g_Xh[input][row][t * 4] = *(uint2*)h;
    *(uint2*)&g_Xl[input][row][t * 4] = *(uint2*)l;
}

// ---------------------------------------------------------------------------
// W conversion: fp32 [k][l] -> fp16 hi/lo planes of (1024*W)^T, [n][k].
// ---------------------------------------------------------------------------
__global__ __launch_bounds__(256)
void wconv_kernel(const float* __restrict__ Wy_h, const float* __restrict__ Wg_h,
                  const float* __restrict__ Wy_q, const float* __restrict__ Wg_q)
{
    __shared__ float tile[32][33];
    const int tx = threadIdx.x, ty = threadIdx.y;
    const int kt = blockIdx.x, nt = blockIdx.y, inp = blockIdx.z;
    const float* W;
    int lbase;
    if (nt * 32 < 512) { W = inp ? Wy_q : Wy_h; lbase = nt * 32; }
    else               { W = inp ? Wg_q : Wg_h; lbase = nt * 32 - 512; }
    #pragma unroll
    for (int r = 0; r < 4; r++)
        tile[ty + r * 8][tx] = W[(size_t)(kt * 32 + ty + r * 8) * 512 + lbase + tx];
    __syncthreads();
    #pragma unroll
    for (int r = 0; r < 4; r++) {
        int nl = ty + r * 8;
        int n  = nt * 32 + nl;
        int k  = kt * 32 + tx;
        float f = tile[tx][nl] * 1024.0f;          // scale avoids fp16 denormal lo
        __half hi = __float2half_rn(f);
        __half lo = __float2half_rn(f - __half2float(hi));
        g_Wh[inp][n][k] = hi;
        g_Wl[inp][n][k] = lo;
    }
}

// ---------------------------------------------------------------------------
// HMMA GEMM + fused gated epilogue.
// CTA: 128 rows x 128 cols (64 u-l's + 64 v-l's), 48 K-chunks of 64 halves.
// Warp layout: 4 (M) x 2 (N). Warp tile: 32 rows x (32 u-cols + 32 v-cols),
// so each l's u/v pair stays in-warp for the epilogue.
// grid (80, 8, 2), block 256. smem 2 stages x 32KB, SW128 swizzled.
// ---------------------------------------------------------------------------
__global__ __launch_bounds__(256)
void gemm_hmma(const float* __restrict__ by_h, const float* __restrict__ bg_h,
               const float* __restrict__ by_q, const float* __restrict__ bg_q)
{
    extern __shared__ char smem[];
    const uint32_t sbase = smem_u32(smem);
    const int tid = threadIdx.x, wid = tid >> 5, lane = tid & 31;
    const int input = blockIdx.z, lc = blockIdx.y;
    const int m0 = blockIdx.x * 128;

    const __half* Xh = &g_Xh[input][0][0];
    const __half* Xl = &g_Xl[input][0][0];
    const __half* Wh = &g_Wh[input][0][0];
    const __half* Wl = &g_Wl[input][0][0];
    const float* by_ = input ? by_q : by_h;
    const float* bg_ = input ? bg_q : bg_h;

    // loaders (8 x 16B per chunk: 4 A rows-groups + 4 B)
    const int ldrow = tid >> 3;        // 0..31 (+i*32)
    const int ldseg = tid & 7;

    // warp tiling
    const int mw = wid >> 1;           // 0..3
    const int nw = wid & 1;            // 0..1
    const int q  = lane >> 3;
    const int r  = lane & 7;
    const int tq = lane & 3;
    const int grow = lane >> 2;        // 0..7

    const uint32_t rx   = (uint32_t)(r << 4);
    const uint32_t aq16 = (uint32_t)((q >> 1) * 16);
    const uint32_t bq16 = (uint32_t)((q & 1) * 16);
    // A row offsets per m-tile (mt in {0,1})
    uint32_t a_rowo[2];
    #pragma unroll
    for (int mt = 0; mt < 2; mt++)
        a_rowo[mt] = (uint32_t)((mw * 32 + mt * 16 + (q & 1) * 8 + r) * 128);
    // B row offsets per bt (u tiles, v tiles)
    uint32_t bu_rowo[2], bv_rowo[2];
    #pragma unroll
    for (int bt = 0; bt < 2; bt++) {
        bu_rowo[bt] = (uint32_t)((nw * 32 + bt * 16 + (q >> 1) * 8 + r) * 128);
        bv_rowo[bt] = (uint32_t)((64 + nw * 32 + bt * 16 + (q >> 1) * 8 + r) * 128);
    }

    float cu[2][4][4], cv[2][4][4];
    #pragma unroll
    for (int mt = 0; mt < 2; mt++)
        #pragma unroll
        for (int ut = 0; ut < 4; ut++)
            #pragma unroll
            for (int e = 0; e < 4; e++) { cu[mt][ut][e] = 0.f; cv[mt][ut][e] = 0.f; }

    auto load_chunk = [&](int kc) {
        const int st = kc & 1;
        const int p  = kc >> 4;
        const int ko = (kc & 15) * 64;
        const __half* As = (p == 1) ? Xl : Xh;
        const __half* Bs = (p == 2) ? Wl : Wh;
        const uint32_t sa = sbase + st * 32768;
        const uint32_t sb = sa + 16384;
        #pragma unroll
        for (int i = 0; i < 4; i++) {
            int row = i * 32 + ldrow;
            const void* src = As + ((size_t)(m0 + row) << 10) + ko + ldseg * 8;
            cp16(sa + SWZ(row * 128 + ldseg * 16), src);
        }
        #pragma unroll
        for (int i = 0; i < 4; i++) {
            int row = i * 32 + ldrow;
            int ng  = (row < 64) ? (lc * 64 + row) : (448 + lc * 64 + row);
            const void* src = Bs + ((size_t)ng << 10) + ko + ldseg * 8;
            cp16(sb + SWZ(row * 128 + ldseg * 16), src);
        }
        CP_COMMIT();
    };

    load_chunk(0);

    #pragma unroll 1
    for (int kc = 0; kc < NKCH; kc++) {
        __syncthreads();
        if (kc + 1 < NKCH) {
            load_chunk(kc + 1);
            asm volatile("cp.async.wait_group 1;" ::: "memory");
        } else {
            asm volatile("cp.async.wait_group 0;" ::: "memory");
        }
        __syncthreads();

        const uint32_t sa = sbase + (kc & 1) * 32768;
        const uint32_t sb = sa + 16384;

        #pragma unroll
        for (int s = 0; s < 4; s++) {
            const uint32_t cba = ((uint32_t)(s * 32) + aq16) ^ rx;
            const uint32_t cbb = ((uint32_t)(s * 32) + bq16) ^ rx;
            uint32_t a[2][4];
            #pragma unroll
            for (int mt = 0; mt < 2; mt++)
                LDSM4(a[mt][0], a[mt][1], a[mt][2], a[mt][3], sa + a_rowo[mt] + cba);
            uint32_t bu[2][4], bv[2][4];
            #pragma unroll
            for (int bt = 0; bt < 2; bt++) {
                LDSM4(bu[bt][0], bu[bt][1], bu[bt][2], bu[bt][3], sb + bu_rowo[bt] + cbb);
                LDSM4(bv[bt][0], bv[bt][1], bv[bt][2], bv[bt][3], sb + bv_rowo[bt] + cbb);
            }
            #pragma unroll
            for (int mt = 0; mt < 2; mt++) {
                #pragma unroll
                for (int bt = 0; bt < 2; bt++) {
                    MMA16816(cu[mt][2 * bt],     a[mt][0], a[mt][1], a[mt][2], a[mt][3], bu[bt][0], bu[bt][1]);
                    MMA16816(cu[mt][2 * bt + 1], a[mt][0], a[mt][1], a[mt][2], a[mt][3], bu[bt][2], bu[bt][3]);
                    MMA16816(cv[mt][2 * bt],     a[mt][0], a[mt][1], a[mt][2], a[mt][3], bv[bt][0], bv[bt][1]);
                    MMA16816(cv[mt][2 * bt + 1], a[mt][0], a[mt][1], a[mt][2], a[mt][3], bv[bt][2], bv[bt][3]);
                }
            }
        }
    }

    // ---- fused epilogue ----
    __syncthreads();                      // smem free for reduction buffer
    float* red = (float*)smem;            // [128][2]
    const float INV = 1.0f / 1024.0f;
    #pragma unroll
    for (int mt = 0; mt < 2; mt++) {
        float p0 = 0.f, p1 = 0.f;
        #pragma unroll
        for (int ut = 0; ut < 4; ut++) {
            #pragma unroll
            for (int e = 0; e < 2; e++) {
                int l = lc * 64 + nw * 32 + ut * 8 + tq * 2 + e;
                float byv = __ldg(by_ + l);
                float bgv = __ldg(bg_ + l);
                float wv  = g_wvec[input][l];
                float u0 = cu[mt][ut][e] * INV + byv;
                float v0 = cv[mt][ut][e] * INV + bgv;
                p0 += tanhf(u0) * (1.f / (1.f + expf(-v0))) * wv;
                float u1 = cu[mt][ut][2 + e] * INV + byv;
                float v1 = cv[mt][ut][2 + e] * INV + bgv;
                p1 += tanhf(u1) * (1.f / (1.f + expf(-v1))) * wv;
            }
        }
        p0 += __shfl_down_sync(0xFFFFFFFF, p0, 2);
        p0 += __shfl_down_sync(0xFFFFFFFF, p0, 1);
        p1 += __shfl_down_sync(0xFFFFFFFF, p1, 2);
        p1 += __shfl_down_sync(0xFFFFFFFF, p1, 1);
        if (tq == 0) {
            int row = mw * 32 + mt * 16 + grow;
            red[row * 2 + nw]       = p0;
            red[(row + 8) * 2 + nw] = p1;
        }
    }
    __syncthreads();
    if (tid < 128)
        g_tpart[input][m0 + tid][lc] = red[tid * 2] + red[tid * 2 + 1];
}

// ---------------------------------------------------------------------------
// Final: logits + Gumbel, argmax over prefix, one-hot write.
// ---------------------------------------------------------------------------
__global__ void final_kernel(const float* __restrict__ noise,
                             const float* __restrict__ Wa, const float* __restrict__ ba,
                             float* __restrict__ out)
{
    int t = blockIdx.x * blockDim.x + threadIdx.x;
    if (t >= BRD) return;
    int b = t / RR;
    int i = t % RR;

    float Wa0 = Wa[0], Wa1 = Wa[1], ba0 = ba[0], c0 = g_c0;
    float tq = 0.f;
    #pragma unroll
    for (int c = 0; c < NLCH; c++) tq += g_tpart[1][t][c];

    float best = -3.4e38f;
    int bj = 0;
    for (int j = 0; j <= i; j++) {
        float th = 0.f;
        #pragma unroll
        for (int c = 0; c < NLCH; c++) th += g_tpart[0][b * RR + j][c];
        float score = tq + th + c0;
        float logit = score * Wa0 + (float)(i - j + 1) * Wa1 + ba0;
        float ns = noise[(size_t)b * RR * RR + i * RR + j];
        float gm = -logf(1e-10f - logf(ns + 1e-10f));
        float z  = logit + gm;
        if (z > best) { best = z; bj = j; }   // strict > keeps first max
    }
    float* o = out + (size_t)b * RR * RR + (size_t)i * RR;
    #pragma unroll
    for (int j = 0; j < RR; j++) o[j] = (j == bj) ? 1.f : 0.f;
}

// ---------------------------------------------------------------------------
extern "C" void kernel_launch(void* const* d_in, const int* in_sizes, int n_in,
                              void* d_out, int out_size)
{
    const float* hist  = (const float*)d_in[0];
    const float* ques  = (const float*)d_in[1];
    const float* noise = (const float*)d_in[2];
    const float* Wy_h  = (const float*)d_in[3];
    const float* by_h  = (const float*)d_in[4];
    const float* Wg_h  = (const float*)d_in[5];
    const float* bg_h  = (const float*)d_in[6];
    const float* Wy_q  = (const float*)d_in[7];
    const float* by_q  = (const float*)d_in[8];
    const float* Wg_q  = (const float*)d_in[9];
    const float* bg_q  = (const float*)d_in[10];
    const float* W1    = (const float*)d_in[11];
    const float* b1    = (const float*)d_in[12];
    const float* W2    = (const float*)d_in[13];
    const float* b2    = (const float*)d_in[14];
    const float* Wa    = (const float*)d_in[15];
    const float* ba    = (const float*)d_in[16];
    float* out = (float*)d_out;

    cudaFuncSetAttribute(gemm_hmma, cudaFuncAttributeMaxDynamicSharedMemorySize, 65536);

    prep_kernel<<<256, 128>>>(W1, b1, W2, b2);
    xconv_kernel<<<dim3(BRD, 2), 256>>>(hist, ques);
    wconv_kernel<<<dim3(32, 32, 2), dim3(32, 8)>>>(Wy_h, Wg_h, Wy_q, Wg_q);

    gemm_hmma<<<dim3(80, NLCH, 2), 256, 65536>>>(by_h, bg_h, by_q, bg_q);

    final_kernel<<<(BRD + 255) / 256, 256>>>(noise, Wa, ba, out);
}

// round 7
// speedup vs baseline: 2.6848x; 1.0065x over previous
#include <cuda_runtime.h>
#include <cuda_fp16.h>
#include <math.h>
#include <stdint.h>

// Problem constants (B=1024, R=10, L=512)
#define RR   10
#define LL   512
#define KK   1024      // 2L
#define BRD  10240     // B*R
#define NLCH 8         // l-chunks of 64
#define NKCH 48        // 3 plane-pairs * 16 k-chunks of 64 halves

// ---------------------------------------------------------------------------
// Static device scratch (no runtime allocation allowed)
// ---------------------------------------------------------------------------
__device__ __half g_Xh[2][BRD][KK];     // fp16 hi plane of X
__device__ __half g_Xl[2][BRD][KK];     // fp16 lo plane of X
__device__ __half g_Wh[2][1024][KK];    // fp16 hi plane of 1024*W^T (n<512: Wy, else Wg)
__device__ __half g_Wl[2][1024][KK];    // fp16 lo plane
__device__ float  g_tpart[2][BRD][NLCH];
__device__ float  g_wvec[2][LL];        // [0]=wh=W1[:L]@W2, [1]=wq=W1[L:]@W2
__device__ float  g_c0;                 // b1.W2 + b2

// ---------------------------------------------------------------------------
// helpers
// ---------------------------------------------------------------------------
__device__ __forceinline__ uint32_t smem_u32(const void* p) {
    uint32_t a;
    asm("{ .reg .u64 t; cvta.to.shared.u64 t, %1; cvt.u32.u64 %0, t; }" : "=r"(a) : "l"(p));
    return a;
}
#define SWZ(o) ((uint32_t)(o) ^ ((((uint32_t)(o)) >> 3) & 0x70))

__device__ __forceinline__ void cp16(uint32_t dst, const void* src) {
    asm volatile("cp.async.cg.shared.global [%0], [%1], 16;" :: "r"(dst), "l"(src) : "memory");
}
#define CP_COMMIT() asm volatile("cp.async.commit_group;" ::: "memory")

#define LDSM4(r0, r1, r2, r3, addr) \
    asm volatile("ldmatrix.sync.aligned.m8n8.x4.shared.b16 {%0,%1,%2,%3}, [%4];" \
                 : "=r"(r0), "=r"(r1), "=r"(r2), "=r"(r3) : "r"(addr))

#define MMA16816(c, a0, a1, a2, a3, b0, b1) \
    asm volatile("mma.sync.aligned.m16n8k16.row.col.f32.f16.f16.f32 " \
                 "{%0,%1,%2,%3}, {%4,%5,%6,%7}, {%8,%9}, {%0,%1,%2,%3};" \
                 : "+f"((c)[0]), "+f"((c)[1]), "+f"((c)[2]), "+f"((c)[3]) \
                 : "r"(a0), "r"(a1), "r"(a2), "r"(a3), "r"(b0), "r"(b1))

// ---------------------------------------------------------------------------
// Prep: wvec, c0
// ---------------------------------------------------------------------------
__global__ __launch_bounds__(128)
void prep_kernel(const float* __restrict__ W1, const float* __restrict__ b1,
                 const float* __restrict__ W2, const float* __restrict__ b2)
{
    const int warp = threadIdx.x >> 5;
    const int lane = threadIdx.x & 31;
    const int idx  = blockIdx.x * 4 + warp;
    float s = 0.f;
    #pragma unroll 4
    for (int m = lane; m < LL; m += 32)
        s += W1[(size_t)idx * LL + m] * W2[m];
    #pragma unroll
    for (int o = 16; o > 0; o >>= 1) s += __shfl_down_sync(0xFFFFFFFF, s, o);
    if (lane == 0) {
        if (idx < LL) g_wvec[0][idx] = s;
        else          g_wvec[1][idx - LL] = s;
    }
    if (blockIdx.x == 0 && warp == 0) {
        float c = 0.f;
        #pragma unroll 4
        for (int m = lane; m < LL; m += 32) c += b1[m] * W2[m];
        #pragma unroll
        for (int o = 16; o > 0; o >>= 1) c += __shfl_down_sync(0xFFFFFFFF, c, o);
        if (lane == 0) g_c0 = c + b2[0];
    }
}

// ---------------------------------------------------------------------------
// X conversion: fp32 -> fp16 hi/lo planes. grid (10240, 2), block 256.
// ---------------------------------------------------------------------------
__global__ __launch_bounds__(256)
void xconv_kernel(const float* __restrict__ hist, const float* __restrict__ ques)
{
    const int input = blockIdx.y;
    const int row   = blockIdx.x;
    const int t     = threadIdx.x;
    const float* X  = input ? ques : hist;
    float4 f = *(const float4*)(X + (size_t)row * KK + t * 4);
    float fv[4] = {f.x, f.y, f.z, f.w};
    __half h[4], l[4];
    #pragma unroll
    for (int e = 0; e < 4; e++) {
        h[e] = __float2half_rn(fv[e]);
        l[e] = __float2half_rn(fv[e] - __half2float(h[e]));
    }
    *(uint2*)&g_Xh[input][row][t * 4] = *(uint2*)h;
    *(uint2*)&g_Xl[input][row][t * 4] = *(uint2*)l;
}

// ---------------------------------------------------------------------------
// W conversion: fp32 [k][l] -> fp16 hi/lo planes of (1024*W)^T, [n][k].
// ---------------------------------------------------------------------------
__global__ __launch_bounds__(256)
void wconv_kernel(const float* __restrict__ Wy_h, const float* __restrict__ Wg_h,
                  const float* __restrict__ Wy_q, const float* __restrict__ Wg_q)
{
    __shared__ float tile[32][33];
    const int tx = threadIdx.x, ty = threadIdx.y;
    const int kt = blockIdx.x, nt = blockIdx.y, inp = blockIdx.z;
    const float* W;
    int lbase;
    if (nt * 32 < 512) { W = inp ? Wy_q : Wy_h; lbase = nt * 32; }
    else               { W = inp ? Wg_q : Wg_h; lbase = nt * 32 - 512; }
    #pragma unroll
    for (int r = 0; r < 4; r++)
        tile[ty + r * 8][tx] = W[(size_t)(kt * 32 + ty + r * 8) * 512 + lbase + tx];
    __syncthreads();
    #pragma unroll
    for (int r = 0; r < 4; r++) {
        int nl = ty + r * 8;
        int n  = nt * 32 + nl;
        int k  = kt * 32 + tx;
        float f = tile[tx][nl] * 1024.0f;          // scale avoids fp16 denormal lo
        __half hi = __float2half_rn(f);
        __half lo = __float2half_rn(f - __half2float(hi));
        g_Wh[inp][n][k] = hi;
        g_Wl[inp][n][k] = lo;
    }
}

// ---------------------------------------------------------------------------
// HMMA GEMM + fused gated epilogue, 3-stage cp.async pipeline.
// CTA: 128 rows x 128 cols (64 u-l's + 64 v-l's), 48 K-chunks of 64 halves.
// Warp layout 4(M) x 2(N); warp tile 32 rows x (32 u + 32 v cols).
// grid (80, 8, 2), block 256. smem 3 stages x 32KB = 96KB, SW128 swizzled.
// ---------------------------------------------------------------------------
__global__ __launch_bounds__(256, 2)
void gemm_hmma(const float* __restrict__ by_h, const float* __restrict__ bg_h,
               const float* __restrict__ by_q, const float* __restrict__ bg_q)
{
    extern __shared__ char smem[];
    const uint32_t sbase = smem_u32(smem);
    const int tid = threadIdx.x, wid = tid >> 5, lane = tid & 31;
    const int input = blockIdx.z, lc = blockIdx.y;
    const int m0 = blockIdx.x * 128;

    const __half* Xh = &g_Xh[input][0][0];
    const __half* Xl = &g_Xl[input][0][0];
    const __half* Wh = &g_Wh[input][0][0];
    const __half* Wl = &g_Wl[input][0][0];
    const float* by_ = input ? by_q : by_h;
    const float* bg_ = input ? bg_q : bg_h;

    // loaders (8 x 16B per chunk: 4 A row-groups + 4 B)
    const int ldrow = tid >> 3;        // 0..31 (+i*32)
    const int ldseg = tid & 7;

    // warp tiling
    const int mw = wid >> 1;           // 0..3
    const int nw = wid & 1;            // 0..1
    const int q  = lane >> 3;
    const int r  = lane & 7;
    const int tq = lane & 3;
    const int grow = lane >> 2;        // 0..7

    const uint32_t rx   = (uint32_t)(r << 4);
    const uint32_t aq16 = (uint32_t)((q >> 1) * 16);
    const uint32_t bq16 = (uint32_t)((q & 1) * 16);
    uint32_t a_rowo[2];
    #pragma unroll
    for (int mt = 0; mt < 2; mt++)
        a_rowo[mt] = (uint32_t)((mw * 32 + mt * 16 + (q & 1) * 8 + r) * 128);
    uint32_t bu_rowo[2], bv_rowo[2];
    #pragma unroll
    for (int bt = 0; bt < 2; bt++) {
        bu_rowo[bt] = (uint32_t)((nw * 32 + bt * 16 + (q >> 1) * 8 + r) * 128);
        bv_rowo[bt] = (uint32_t)((64 + nw * 32 + bt * 16 + (q >> 1) * 8 + r) * 128);
    }

    float cu[2][4][4], cv[2][4][4];
    #pragma unroll
    for (int mt = 0; mt < 2; mt++)
        #pragma unroll
        for (int ut = 0; ut < 4; ut++)
            #pragma unroll
            for (int e = 0; e < 4; e++) { cu[mt][ut][e] = 0.f; cv[mt][ut][e] = 0.f; }

    auto load_chunk = [&](int kc, int st) {
        const int p  = kc >> 4;
        const int ko = (kc & 15) * 64;
        const __half* As = (p == 1) ? Xl : Xh;
        const __half* Bs = (p == 2) ? Wl : Wh;
        const uint32_t sa = sbase + (uint32_t)st * 32768u;
        const uint32_t sb = sa + 16384;
        #pragma unroll
        for (int i = 0; i < 4; i++) {
            int row = i * 32 + ldrow;
            const void* src = As + ((size_t)(m0 + row) << 10) + ko + ldseg * 8;
            cp16(sa + SWZ(row * 128 + ldseg * 16), src);
        }
        #pragma unroll
        for (int i = 0; i < 4; i++) {
            int row = i * 32 + ldrow;
            int ng  = (row < 64) ? (lc * 64 + row) : (448 + lc * 64 + row);
            const void* src = Bs + ((size_t)ng << 10) + ko + ldseg * 8;
            cp16(sb + SWZ(row * 128 + ldseg * 16), src);
        }
        CP_COMMIT();
    };

    // prologue: stages 0 and 1 in flight
    load_chunk(0, 0);
    load_chunk(1, 1);

    int st_cur = 0;   // stage of chunk kc
    int st_nxt = 2;   // stage for chunk kc+2

    #pragma unroll 1
    for (int kc = 0; kc < NKCH; kc++) {
        // wait for chunk kc (leave at most 1 newer group in flight)
        if (kc + 1 < NKCH) {
            asm volatile("cp.async.wait_group 1;" ::: "memory");
        } else {
            asm volatile("cp.async.wait_group 0;" ::: "memory");
        }
        __syncthreads();   // all warps past compute of kc-1; stage st_nxt reusable

        if (kc + 2 < NKCH)
            load_chunk(kc + 2, st_nxt);   // overlaps compute below

        const uint32_t sa = sbase + (uint32_t)st_cur * 32768u;
        const uint32_t sb = sa + 16384;

        #pragma unroll
        for (int s = 0; s < 4; s++) {
            const uint32_t cba = ((uint32_t)(s * 32) + aq16) ^ rx;
            const uint32_t cbb = ((uint32_t)(s * 32) + bq16) ^ rx;
            uint32_t a[2][4];
            #pragma unroll
            for (int mt = 0; mt < 2; mt++)
                LDSM4(a[mt][0], a[mt][1], a[mt][2], a[mt][3], sa + a_rowo[mt] + cba);
            uint32_t bu[2][4], bv[2][4];
            #pragma unroll
            for (int bt = 0; bt < 2; bt++) {
                LDSM4(bu[bt][0], bu[bt][1], bu[bt][2], bu[bt][3], sb + bu_rowo[bt] + cbb);
                LDSM4(bv[bt][0], bv[bt][1], bv[bt][2], bv[bt][3], sb + bv_rowo[bt] + cbb);
            }
            #pragma unroll
            for (int mt = 0; mt < 2; mt++) {
                #pragma unroll
                for (int bt = 0; bt < 2; bt++) {
                    MMA16816(cu[mt][2 * bt],     a[mt][0], a[mt][1], a[mt][2], a[mt][3], bu[bt][0], bu[bt][1]);
                    MMA16816(cu[mt][2 * bt + 1], a[mt][0], a[mt][1], a[mt][2], a[mt][3], bu[bt][2], bu[bt][3]);
                    MMA16816(cv[mt][2 * bt],     a[mt][0], a[mt][1], a[mt][2], a[mt][3], bv[bt][0], bv[bt][1]);
                    MMA16816(cv[mt][2 * bt + 1], a[mt][0], a[mt][1], a[mt][2], a[mt][3], bv[bt][2], bv[bt][3]);
                }
            }
        }

        st_cur = (st_cur == 2) ? 0 : st_cur + 1;
        st_nxt = (st_nxt == 2) ? 0 : st_nxt + 1;
    }

    // ---- fused epilogue ----
    __syncthreads();                      // smem free for reduction buffer
    float* red = (float*)smem;            // [128][2]
    const float INV = 1.0f / 1024.0f;
    #pragma unroll
    for (int mt = 0; mt < 2; mt++) {
        float p0 = 0.f, p1 = 0.f;
        #pragma unroll
        for (int ut = 0; ut < 4; ut++) {
            #pragma unroll
            for (int e = 0; e < 2; e++) {
                int l = lc * 64 + nw * 32 + ut * 8 + tq * 2 + e;
                float byv = __ldg(by_ + l);
                float bgv = __ldg(bg_ + l);
                float wv  = g_wvec[input][l];
                float u0 = cu[mt][ut][e] * INV + byv;
                float v0 = cv[mt][ut][e] * INV + bgv;
                p0 += tanhf(u0) * (1.f / (1.f + expf(-v0))) * wv;
                float u1 = cu[mt][ut][2 + e] * INV + byv;
                float v1 = cv[mt][ut][2 + e] * INV + bgv;
                p1 += tanhf(u1) * (1.f / (1.f + expf(-v1))) * wv;
            }
        }
        p0 += __shfl_down_sync(0xFFFFFFFF, p0, 2);
        p0 += __shfl_down_sync(0xFFFFFFFF, p0, 1);
        p1 += __shfl_down_sync(0xFFFFFFFF, p1, 2);
        p1 += __shfl_down_sync(0xFFFFFFFF, p1, 1);
        if (tq == 0) {
            int row = mw * 32 + mt * 16 + grow;
            red[row * 2 + nw]       = p0;
            red[(row + 8) * 2 + nw] = p1;
        }
    }
    __syncthreads();
    if (tid < 128)
        g_tpart[input][m0 + tid][lc] = red[tid * 2] + red[tid * 2 + 1];
}

// ---------------------------------------------------------------------------
// Final: logits + Gumbel, argmax over prefix, one-hot write.
// ---------------------------------------------------------------------------
__global__ void final_kernel(const float* __restrict__ noise,
                             const float* __restrict__ Wa, const float* __restrict__ ba,
                             float* __restrict__ out)
{
    int t = blockIdx.x * blockDim.x + threadIdx.x;
    if (t >= BRD) return;
    int b = t / RR;
    int i = t % RR;

    float Wa0 = Wa[0], Wa1 = Wa[1], ba0 = ba[0], c0 = g_c0;
    float tq = 0.f;
    #pragma unroll
    for (int c = 0; c < NLCH; c++) tq += g_tpart[1][t][c];

    float best = -3.4e38f;
    int bj = 0;
    for (int j = 0; j <= i; j++) {
        float th = 0.f;
        #pragma unroll
        for (int c = 0; c < NLCH; c++) th += g_tpart[0][b * RR + j][c];
        float score = tq + th + c0;
        float logit = score * Wa0 + (float)(i - j + 1) * Wa1 + ba0;
        float ns = noise[(size_t)b * RR * RR + i * RR + j];
        float gm = -logf(1e-10f - logf(ns + 1e-10f));
        float z  = logit + gm;
        if (z > best) { best = z; bj = j; }   // strict > keeps first max
    }
    float* o = out + (size_t)b * RR * RR + (size_t)i * RR;
    #pragma unroll
    for (int j = 0; j < RR; j++) o[j] = (j == bj) ? 1.f : 0.f;
}

// ---------------------------------------------------------------------------
extern "C" void kernel_launch(void* const* d_in, const int* in_sizes, int n_in,
                              void* d_out, int out_size)
{
    const float* hist  = (const float*)d_in[0];
    const float* ques  = (const float*)d_in[1];
    const float* noise = (const float*)d_in[2];
    const float* Wy_h  = (const float*)d_in[3];
    const float* by_h  = (const float*)d_in[4];
    const float* Wg_h  = (const float*)d_in[5];
    const float* bg_h  = (const float*)d_in[6];
    const float* Wy_q  = (const float*)d_in[7];
    const float* by_q  = (const float*)d_in[8];
    const float* Wg_q  = (const float*)d_in[9];
    const float* bg_q  = (const float*)d_in[10];
    const float* W1    = (const float*)d_in[11];
    const float* b1    = (const float*)d_in[12];
    const float* W2    = (const float*)d_in[13];
    const float* b2    = (const float*)d_in[14];
    const float* Wa    = (const float*)d_in[15];
    const float* ba    = (const float*)d_in[16];
    float* out = (float*)d_out;

    cudaFuncSetAttribute(gemm_hmma, cudaFuncAttributeMaxDynamicSharedMemorySize, 98304);

    prep_kernel<<<256, 128>>>(W1, b1, W2, b2);
    xconv_kernel<<<dim3(BRD, 2), 256>>>(hist, ques);
    wconv_kernel<<<dim3(32, 32, 2), dim3(32, 8)>>>(Wy_h, Wg_h, Wy_q, Wg_q);

    gemm_hmma<<<dim3(80, NLCH, 2), 256, 98304>>>(by_h, bg_h, by_q, bg_q);

    final_kernel<<<(BRD + 255) / 256, 256>>>(noise, Wa, ba, out);
}